// round 1
// baseline (speedup 1.0000x reference)
#include <cuda_runtime.h>
#include <cuda_bf16.h>

// SSM kernel: out[l, i] = exp(l * a_i) * (B_i * C_i) + D,  a_i = A[i][i]
// L = 262144, n = 256. Output 256 MiB fp32 -> pure streaming-store bound.
//
// Strategy: geometric recurrence per column (pm *= exp(a)) instead of a
// per-element exp (which would be MUFU-bound at ~13x the memory roofline).
// Each thread re-anchors its chunk with one exact exp2f, so drift <= 128 ulp.

#define N_COLS 256
#define CGROUPS 64      // column groups of 4 (float4 store)
#define RY 4            // row sub-chunks per block
#define ROWS_PER_THREAD 128
#define ROWS_PER_BLOCK (RY * ROWS_PER_THREAD)   // 512

__global__ __launch_bounds__(256, 8)
void ssm_kernel(const float* __restrict__ A,
                const float* __restrict__ B,
                const float* __restrict__ C,
                const float* __restrict__ D,
                float4* __restrict__ out)
{
    const int tx = threadIdx.x & 63;        // column group: cols 4*tx .. 4*tx+3
    const int ty = threadIdx.x >> 6;        // row sub-chunk within block
    const long long row0 = (long long)blockIdx.x * ROWS_PER_BLOCK
                         + (long long)ty * ROWS_PER_THREAD;

    const float d = D[0];

    float r[4], pm[4], bc[4];
#pragma unroll
    for (int k = 0; k < 4; k++) {
        const int j = tx * 4 + k;
        const float a = A[j * N_COLS + j];          // diag element (log factor)
        r[k]  = __expf(a);                          // per-row ratio
        // exact re-anchor at chunk start: exp(row0 * a) = 2^(row0*a*log2e)
        pm[k] = exp2f((float)row0 * a * 1.4426950408889634f);
        bc[k] = B[j] * C[j];
    }

    // index in float4 units: each row is 64 float4
    long long base = row0 * (long long)CGROUPS + tx;

#pragma unroll 4
    for (int l = 0; l < ROWS_PER_THREAD; l++) {
        float4 v;
        v.x = fmaf(pm[0], bc[0], d);
        v.y = fmaf(pm[1], bc[1], d);
        v.z = fmaf(pm[2], bc[2], d);
        v.w = fmaf(pm[3], bc[3], d);
        out[base] = v;
        base += CGROUPS;
        pm[0] *= r[0];
        pm[1] *= r[1];
        pm[2] *= r[2];
        pm[3] *= r[3];
    }
}

extern "C" void kernel_launch(void* const* d_in, const int* in_sizes, int n_in,
                              void* d_out, int out_size)
{
    // Inputs per reference order: L (scalar), A (n*n), B (n), C (n), D (1).
    // Be robust to whether the scalar L is materialized as an input.
    int base = 0;
    if (n_in >= 5) base = n_in - 4;          // skip leading scalar(s); A,B,C,D last 4
    const float* A = (const float*)d_in[base + 0];
    const float* B = (const float*)d_in[base + 1];
    const float* C = (const float*)d_in[base + 2];
    const float* D = (const float*)d_in[base + 3];

    const long long L = (long long)out_size / N_COLS;   // 262144
    const int blocks = (int)(L / ROWS_PER_BLOCK);       // 512

    ssm_kernel<<<blocks, 256>>>(A, B, C, D, (float4*)d_out);
}

// round 2
// speedup vs baseline: 1.1055x; 1.1055x over previous
#include <cuda_runtime.h>
#include <cuda_bf16.h>

// SSM kernel: out[l, i] = exp(l * a_i) * (B_i * C_i) + D,  a_i = A[i][i]
// L = 262144, n = 256. Output 256 MiB fp32 -> pure streaming-store bound.
//
// R1 finding: 512-block launch left a 16% CTA-imbalance tail (148*3+68).
// R2: balanced grid of 148*4 = 592 blocks, grid-stride over 4096 chunks of
// 64 rows (per-SM imbalance ~1.2%). Geometric recurrence per column with a
// precomputed "jump" factor to hop between a thread's chunks without MUFU.

#define N_COLS 256
#define CGROUPS 64              // 64 float4 per row
#define CHUNK_ROWS 64           // rows per chunk (per block per grid-stride step)
#define TY 4                    // row sub-chunks per block
#define RPT 16                  // rows per thread per chunk (CHUNK_ROWS/TY)
#define GRID_BLOCKS 592         // 148 SMs * 4 CTAs, exactly balanced

__global__ __launch_bounds__(256, 8)
void ssm_kernel(const float* __restrict__ A,
                const float* __restrict__ B,
                const float* __restrict__ C,
                const float* __restrict__ D,
                float4* __restrict__ out,
                int nchunks)
{
    const int tx = threadIdx.x & 63;        // column group: cols 4*tx .. 4*tx+3
    const int ty = threadIdx.x >> 6;        // row sub-chunk within chunk

    const float d = D[0];
    const float LOG2E = 1.4426950408889634f;

    // rows skipped when hopping from the end of this thread's rows in one
    // chunk to the start of its rows in its next chunk
    const float hop_rows = (float)((long long)gridDim.x * CHUNK_ROWS - RPT);

    const long long first_row = (long long)blockIdx.x * CHUNK_ROWS
                              + (long long)ty * RPT;

    float r[4], pm[4], bc[4], jmp[4];
#pragma unroll
    for (int k = 0; k < 4; k++) {
        const int j = tx * 4 + k;
        const float a = A[j * N_COLS + j];          // diag (strictly negative)
        r[k]   = __expf(a);                         // per-row decay ratio
        jmp[k] = exp2f(hop_rows * a * LOG2E);       // chunk-hop factor
        pm[k]  = exp2f((float)first_row * a * LOG2E); // exact anchor
        bc[k]  = B[j] * C[j];
    }

    for (int c = blockIdx.x; c < nchunks; c += gridDim.x) {
        long long base = ((long long)c * CHUNK_ROWS + (long long)ty * RPT)
                       * CGROUPS + tx;
#pragma unroll
        for (int l = 0; l < RPT; l++) {
            float4 v;
            v.x = fmaf(pm[0], bc[0], d);
            v.y = fmaf(pm[1], bc[1], d);
            v.z = fmaf(pm[2], bc[2], d);
            v.w = fmaf(pm[3], bc[3], d);
            __stcs(&out[base], v);                  // streaming store, no reuse
            base += CGROUPS;
            pm[0] *= r[0];
            pm[1] *= r[1];
            pm[2] *= r[2];
            pm[3] *= r[3];
        }
        // hop to this thread's rows in the next grid-stride chunk
        pm[0] *= jmp[0];
        pm[1] *= jmp[1];
        pm[2] *= jmp[2];
        pm[3] *= jmp[3];
    }
}

extern "C" void kernel_launch(void* const* d_in, const int* in_sizes, int n_in,
                              void* d_out, int out_size)
{
    // Inputs per reference order: (optional scalar L), A (n*n), B (n), C (n), D (1)
    int base = 0;
    if (n_in >= 5) base = n_in - 4;
    const float* A = (const float*)d_in[base + 0];
    const float* B = (const float*)d_in[base + 1];
    const float* C = (const float*)d_in[base + 2];
    const float* D = (const float*)d_in[base + 3];

    const long long L = (long long)out_size / N_COLS;   // 262144
    const int nchunks = (int)(L / CHUNK_ROWS);          // 4096

    ssm_kernel<<<GRID_BLOCKS, 256>>>(A, B, C, D, (float4*)d_out, nchunks);
}